// round 11
// baseline (speedup 1.0000x reference)
#include <cuda_runtime.h>

#define B_ 16
#define A_ 5
#define C_ 512
#define HW_ 256
#define NC 4
#define CCHUNK 16

// out[(i*B+b)] = local[(i*B+b)] + sum_{j != i, j<n, i<n} warp(local[(j*B+b)], trans[b,i,j])
// warp = bilinear grid_sample chained twice (rotation, then constant translation),
// zero pad, align_corners=False. Geometry channel-invariant AND c0-invariant ->
// tap tables precomputed once per (b,i,jj,pixel) by a tiny kernel into __device__
// globals; main kernel loads them with a few coalesced LDG.128.
// Main loop: float4 channel-vectorized tiles, tileA ping-pong (2 barriers/chunk),
// register prefetch of next chunk. Natural register budget (capping spills, R7).

__device__ float4 g_wA[B_][A_][4][256];   // stage-1 (rotation) bilinear weights
__device__ float4 g_wB[B_][A_][4][256];   // stage-2 (translation) bilinear weights
__device__ uint2  g_ix[B_][A_][4][256];   // .x = packed stage-1 idx, .y = packed stage-2 idx

__global__ void tap_kernel(const float* __restrict__ trans)
{
    const int b = blockIdx.x / A_;
    const int i = blockIdx.x % A_;
    const int t = threadIdx.x;
    const int x = t & 15;
    const int y = t >> 4;

    const float xs = (2.f * (float)x + 1.f) / 16.f - 1.f;
    const float ys = (2.f * (float)y + 1.f) / 16.f - 1.f;

    #pragma unroll
    for (int jj = 0; jj < 4; jj++) {
        const int j = jj + (jj >= i ? 1 : 0);          // skip j == i
        const float* T = trans + (((b * A_ + i) * A_ + j) * 16);
        const float t00 = T[0], t01 = T[1], t03 = T[3];
        const float t10 = T[4], t11 = T[5], t13 = T[7];

        float wA[4], wB[4];
        unsigned pA = 0u, pB = 0u;

        // ---- stage 1: rotation grid ----
        const float gx = t00 * xs + t01 * ys;
        const float gy = t10 * xs + t11 * ys;
        const float ix = ((gx + 1.f) * 16.f - 1.f) * 0.5f;
        const float iy = ((gy + 1.f) * 16.f - 1.f) * 0.5f;
        const float x0f = floorf(ix), y0f = floorf(iy);
        const float fx = ix - x0f,  fy = iy - y0f;
        const int x0 = (int)x0f, y0 = (int)y0f;
        #pragma unroll
        for (int m = 0; m < 4; m++) {
            const int dx = m & 1, dy = m >> 1;
            const int xi = x0 + dx, yi = y0 + dy;
            const float w = (dx ? fx : 1.f - fx) * (dy ? fy : 1.f - fy);
            const bool in = (xi >= 0) & (xi < 16) & (yi >= 0) & (yi < 16);
            wA[m] = in ? w : 0.f;
            pA   |= (unsigned)(in ? (yi * 16 + xi) : 0) << (8 * m);
        }

        // ---- stage 2: translation grid ----
        const float xt = t03 * (1.f / 32.f);      // 4*T03/128
        const float yt = -t13 * (1.f / 32.f);
        const float ix2 = ((xs + xt + 1.f) * 16.f - 1.f) * 0.5f;
        const float iy2 = ((ys + yt + 1.f) * 16.f - 1.f) * 0.5f;
        const float x20f = floorf(ix2), y20f = floorf(iy2);
        const float fx2 = ix2 - x20f,  fy2 = iy2 - y20f;
        const int x20 = (int)x20f, y20 = (int)y20f;
        #pragma unroll
        for (int m = 0; m < 4; m++) {
            const int dx = m & 1, dy = m >> 1;
            const int xi = x20 + dx, yi = y20 + dy;
            const float w = (dx ? fx2 : 1.f - fx2) * (dy ? fy2 : 1.f - fy2);
            const bool in = (xi >= 0) & (xi < 16) & (yi >= 0) & (yi < 16);
            wB[m] = in ? w : 0.f;
            pB   |= (unsigned)(in ? (yi * 16 + xi) : 0) << (8 * m);
        }

        g_wA[b][i][jj][t] = make_float4(wA[0], wA[1], wA[2], wA[3]);
        g_wB[b][i][jj][t] = make_float4(wB[0], wB[1], wB[2], wB[3]);
        g_ix[b][i][jj][t] = make_uint2(pA, pB);
    }
}

__global__ __launch_bounds__(256, 2)
void fuse_kernel(const float* __restrict__ feat,
                 const int* __restrict__ nag,
                 float* __restrict__ out)
{
    __shared__ float4 tileA[2][4][256];   // ping-pong source tiles (4 ch/pixel)
    __shared__ float4 tileR[4][256];      // rotation-sampled intermediates

    const int b  = blockIdx.z;
    const int i  = blockIdx.y;
    const int c0 = blockIdx.x * CCHUNK;
    const int t  = threadIdx.x;

    const int n = nag[b * A_];            // num_agent_tensor[b, 0]
    const bool active = (i < n) && (n > 1);

    const unsigned base = ((unsigned)(i * B_ + b) * C_ + c0) * HW_;
    const float* __restrict__ local = feat + base;
    float* __restrict__ outp        = out  + base;

    // Load per-neighbor tap metadata (coalesced LDG.128 from tables).
    float4   wA[4], wB[4];
    unsigned pA[4], pB[4];
    unsigned off[4];
    bool valid[4];

    #pragma unroll
    for (int jj = 0; jj < 4; jj++) {
        const int j = jj + (jj >= i ? 1 : 0);          // skip j == i
        valid[jj] = active && (j < n);
        off[jj]   = ((unsigned)(j * B_ + b) * C_ + c0) * HW_;
        wA[jj] = g_wA[b][i][jj][t];
        wB[jj] = g_wB[b][i][jj][t];
        const uint2 e = g_ix[b][i][jj][t];
        pA[jj] = e.x;
        pB[jj] = e.y;
    }

    // ---- prologue: prefetch chunk 0 fills into registers ----
    float4 pre[4];
    #pragma unroll
    for (int jj = 0; jj < 4; jj++) {
        if (valid[jj]) {
            const float* src = feat + off[jj];
            pre[jj].x = src[t];
            pre[jj].y = src[HW_ + t];
            pre[jj].z = src[2 * HW_ + t];
            pre[jj].w = src[3 * HW_ + t];
        }
    }

    int p = 0;
    for (int g = 0; g < CCHUNK; g += NC, p ^= 1) {
        // deposit prefetched fills (STS.128, conflict-free)
        #pragma unroll
        for (int jj = 0; jj < 4; jj++) {
            if (valid[jj]) tileA[p][jj][t] = pre[jj];
        }

        float4 acc;
        acc.x = local[(g + 0) * HW_ + t];
        acc.y = local[(g + 1) * HW_ + t];
        acc.z = local[(g + 2) * HW_ + t];
        acc.w = local[(g + 3) * HW_ + t];

        __syncthreads();                  // (a) tileA[p] visible; tileR WAR done

        // prefetch next chunk (latency hidden by stage1+stage2 below)
        if (g + NC < CCHUNK) {
            #pragma unroll
            for (int jj = 0; jj < 4; jj++) {
                if (valid[jj]) {
                    const float* src = feat + off[jj] + (unsigned)(g + NC) * HW_;
                    pre[jj].x = src[t];
                    pre[jj].y = src[HW_ + t];
                    pre[jj].z = src[2 * HW_ + t];
                    pre[jj].w = src[3 * HW_ + t];
                }
            }
        }

        // stage 1: rotation sample -> R tiles (one LDS.128 per tap, 4 channels)
        #pragma unroll
        for (int jj = 0; jj < 4; jj++) {
            if (valid[jj]) {
                const float4 v0 = tileA[p][jj][(pA[jj]      ) & 255];
                const float4 v1 = tileA[p][jj][(pA[jj] >>  8) & 255];
                const float4 v2 = tileA[p][jj][(pA[jj] >> 16) & 255];
                const float4 v3 = tileA[p][jj][(pA[jj] >> 24) & 255];
                const float w0 = wA[jj].x, w1 = wA[jj].y, w2 = wA[jj].z, w3 = wA[jj].w;
                float4 r;
                r.x = w0 * v0.x + w1 * v1.x + w2 * v2.x + w3 * v3.x;
                r.y = w0 * v0.y + w1 * v1.y + w2 * v2.y + w3 * v3.y;
                r.z = w0 * v0.z + w1 * v1.z + w2 * v2.z + w3 * v3.z;
                r.w = w0 * v0.w + w1 * v1.w + w2 * v2.w + w3 * v3.w;
                tileR[jj][t] = r;
            }
        }
        __syncthreads();                  // (b) tileR ready

        // stage 2: translation sample -> accumulate
        #pragma unroll
        for (int jj = 0; jj < 4; jj++) {
            if (valid[jj]) {
                const float4 v0 = tileR[jj][(pB[jj]      ) & 255];
                const float4 v1 = tileR[jj][(pB[jj] >>  8) & 255];
                const float4 v2 = tileR[jj][(pB[jj] >> 16) & 255];
                const float4 v3 = tileR[jj][(pB[jj] >> 24) & 255];
                const float w0 = wB[jj].x, w1 = wB[jj].y, w2 = wB[jj].z, w3 = wB[jj].w;
                acc.x += w0 * v0.x + w1 * v1.x + w2 * v2.x + w3 * v3.x;
                acc.y += w0 * v0.y + w1 * v1.y + w2 * v2.y + w3 * v3.y;
                acc.z += w0 * v0.z + w1 * v1.z + w2 * v2.z + w3 * v3.z;
                acc.w += w0 * v0.w + w1 * v1.w + w2 * v2.w + w3 * v3.w;
            }
        }

        outp[(g + 0) * HW_ + t] = acc.x;
        outp[(g + 1) * HW_ + t] = acc.y;
        outp[(g + 2) * HW_ + t] = acc.z;
        outp[(g + 3) * HW_ + t] = acc.w;
    }
}

extern "C" void kernel_launch(void* const* d_in, const int* in_sizes, int n_in,
                              void* d_out, int out_size)
{
    const float* feat  = (const float*)d_in[0];   // [A*B, C, H, W] f32
    const float* trans = (const float*)d_in[1];   // [B, A, A, 4, 4] f32
    const int*   nag   = (const int*)d_in[2];     // [B, A] int32
    float* out = (float*)d_out;                   // [A*B, C, H, W] f32

    tap_kernel<<<B_ * A_, 256>>>(trans);

    dim3 grid(C_ / CCHUNK, A_, B_);
    fuse_kernel<<<grid, 256>>>(feat, nag, out);
}

// round 12
// speedup vs baseline: 1.3426x; 1.3426x over previous
#include <cuda_runtime.h>

#define B_ 16
#define A_ 5
#define C_ 512
#define HW_ 256
#define NC 4
#define CCHUNK 32

// out[(i*B+b)] = local[(i*B+b)] + sum_{j != i, j<n, i<n} warp(local[(j*B+b)], trans[b,i,j])
// warp = bilinear grid_sample chained twice (rotation, then constant translation),
// zero pad, align_corners=False. Geometry channel-invariant -> register tap tables.
// float4 channel-vectorized tiles; tileA ping-pong (2 barriers/chunk); register
// prefetch of next chunk. XOR swizzle on tile slots (p ^ ((p>>4)&7)) makes the
// bank-group (x^y)%8 instead of x%8, killing cross-row gather conflicts. Swizzle
// baked into packed tap indices + one precomputed store slot: zero inner-loop cost.

__device__ __forceinline__ int swz(int p) { return p ^ ((p >> 4) & 7); }

__global__ __launch_bounds__(256, 2)
void fuse_kernel(const float* __restrict__ feat,
                 const float* __restrict__ trans,
                 const int* __restrict__ nag,
                 float* __restrict__ out)
{
    __shared__ float4 tileA[2][4][256];   // ping-pong source tiles (4 ch/pixel), swizzled slots
    __shared__ float4 tileR[4][256];      // rotation-sampled intermediates, swizzled slots

    const int b  = blockIdx.z;
    const int i  = blockIdx.y;
    const int c0 = blockIdx.x * CCHUNK;
    const int t  = threadIdx.x;
    const int x  = t & 15;
    const int y  = t >> 4;
    const int swt = swz(t);               // this thread's swizzled tile slot

    const int n = nag[b * A_];            // num_agent_tensor[b, 0]
    const bool active = (i < n) && (n > 1);

    const unsigned base = ((unsigned)(i * B_ + b) * C_ + c0) * HW_;
    const float* __restrict__ local = feat + base;
    float* __restrict__ outp        = out  + base;

    // normalized pixel coords (align_corners=False)
    const float xs = (2.f * (float)x + 1.f) / 16.f - 1.f;
    const float ys = (2.f * (float)y + 1.f) / 16.f - 1.f;

    // Per-neighbor tap metadata (channel-invariant). Indices stored pre-swizzled.
    float    wA[4][4], wB[4][4];
    unsigned pA[4], pB[4];                // 4 byte-sized swizzled indices packed per table
    unsigned off[4];                      // neighbor block element offset
    bool valid[4];

    #pragma unroll
    for (int jj = 0; jj < 4; jj++) {
        const int j = jj + (jj >= i ? 1 : 0);          // skip j == i
        const bool v = active && (j < n);
        valid[jj] = v;
        off[jj]   = ((unsigned)(j * B_ + b) * C_ + c0) * HW_;
        pA[jj] = 0u; pB[jj] = 0u;
        #pragma unroll
        for (int m = 0; m < 4; m++) { wA[jj][m] = 0.f; wB[jj][m] = 0.f; }
        if (v) {
            const float* T = trans + (((b * A_ + i) * A_ + j) * 16);
            const float t00 = T[0], t01 = T[1], t03 = T[3];
            const float t10 = T[4], t11 = T[5], t13 = T[7];

            // ---- stage 1: rotation grid ----
            const float gx = t00 * xs + t01 * ys;
            const float gy = t10 * xs + t11 * ys;
            const float ix = ((gx + 1.f) * 16.f - 1.f) * 0.5f;
            const float iy = ((gy + 1.f) * 16.f - 1.f) * 0.5f;
            const float x0f = floorf(ix), y0f = floorf(iy);
            const float fx = ix - x0f,  fy = iy - y0f;
            const int x0 = (int)x0f, y0 = (int)y0f;
            #pragma unroll
            for (int m = 0; m < 4; m++) {
                const int dx = m & 1, dy = m >> 1;
                const int xi = x0 + dx, yi = y0 + dy;
                const float w = (dx ? fx : 1.f - fx) * (dy ? fy : 1.f - fy);
                const bool in = (xi >= 0) & (xi < 16) & (yi >= 0) & (yi < 16);
                wA[jj][m] = in ? w : 0.f;
                pA[jj]  |= (unsigned)swz(in ? (yi * 16 + xi) : 0) << (8 * m);
            }

            // ---- stage 2: translation grid ----
            const float xt = t03 * (1.f / 32.f);      // 4*T03/128
            const float yt = -t13 * (1.f / 32.f);
            const float ix2 = ((xs + xt + 1.f) * 16.f - 1.f) * 0.5f;
            const float iy2 = ((ys + yt + 1.f) * 16.f - 1.f) * 0.5f;
            const float x20f = floorf(ix2), y20f = floorf(iy2);
            const float fx2 = ix2 - x20f,  fy2 = iy2 - y20f;
            const int x20 = (int)x20f, y20 = (int)y20f;
            #pragma unroll
            for (int m = 0; m < 4; m++) {
                const int dx = m & 1, dy = m >> 1;
                const int xi = x20 + dx, yi = y20 + dy;
                const float w = (dx ? fx2 : 1.f - fx2) * (dy ? fy2 : 1.f - fy2);
                const bool in = (xi >= 0) & (xi < 16) & (yi >= 0) & (yi < 16);
                wB[jj][m] = in ? w : 0.f;
                pB[jj]  |= (unsigned)swz(in ? (yi * 16 + xi) : 0) << (8 * m);
            }
        }
    }

    // ---- prologue: prefetch chunk 0 fills into registers ----
    float4 pre[4];
    #pragma unroll
    for (int jj = 0; jj < 4; jj++) {
        if (valid[jj]) {
            const float* src = feat + off[jj];
            pre[jj].x = src[t];
            pre[jj].y = src[HW_ + t];
            pre[jj].z = src[2 * HW_ + t];
            pre[jj].w = src[3 * HW_ + t];
        }
    }

    int p = 0;
    for (int g = 0; g < CCHUNK; g += NC, p ^= 1) {
        // deposit prefetched fills (STS.128 at swizzled slot — conflict-free)
        #pragma unroll
        for (int jj = 0; jj < 4; jj++) {
            if (valid[jj]) tileA[p][jj][swt] = pre[jj];
        }

        float4 acc;
        acc.x = local[(g + 0) * HW_ + t];
        acc.y = local[(g + 1) * HW_ + t];
        acc.z = local[(g + 2) * HW_ + t];
        acc.w = local[(g + 3) * HW_ + t];

        __syncthreads();                  // (a) tileA[p] visible; tileR WAR done

        // prefetch next chunk (latency hidden by stage1+stage2 below)
        if (g + NC < CCHUNK) {
            #pragma unroll
            for (int jj = 0; jj < 4; jj++) {
                if (valid[jj]) {
                    const float* src = feat + off[jj] + (unsigned)(g + NC) * HW_;
                    pre[jj].x = src[t];
                    pre[jj].y = src[HW_ + t];
                    pre[jj].z = src[2 * HW_ + t];
                    pre[jj].w = src[3 * HW_ + t];
                }
            }
        }

        // stage 1: rotation sample -> R tiles (one LDS.128 per tap, 4 channels)
        #pragma unroll
        for (int jj = 0; jj < 4; jj++) {
            if (valid[jj]) {
                const float4 v0 = tileA[p][jj][(pA[jj]      ) & 255];
                const float4 v1 = tileA[p][jj][(pA[jj] >>  8) & 255];
                const float4 v2 = tileA[p][jj][(pA[jj] >> 16) & 255];
                const float4 v3 = tileA[p][jj][(pA[jj] >> 24) & 255];
                const float w0 = wA[jj][0], w1 = wA[jj][1], w2 = wA[jj][2], w3 = wA[jj][3];
                float4 r;
                r.x = w0 * v0.x + w1 * v1.x + w2 * v2.x + w3 * v3.x;
                r.y = w0 * v0.y + w1 * v1.y + w2 * v2.y + w3 * v3.y;
                r.z = w0 * v0.z + w1 * v1.z + w2 * v2.z + w3 * v3.z;
                r.w = w0 * v0.w + w1 * v1.w + w2 * v2.w + w3 * v3.w;
                tileR[jj][swt] = r;
            }
        }
        __syncthreads();                  // (b) tileR ready

        // stage 2: translation sample -> accumulate
        #pragma unroll
        for (int jj = 0; jj < 4; jj++) {
            if (valid[jj]) {
                const float4 v0 = tileR[jj][(pB[jj]      ) & 255];
                const float4 v1 = tileR[jj][(pB[jj] >>  8) & 255];
                const float4 v2 = tileR[jj][(pB[jj] >> 16) & 255];
                const float4 v3 = tileR[jj][(pB[jj] >> 24) & 255];
                const float w0 = wB[jj][0], w1 = wB[jj][1], w2 = wB[jj][2], w3 = wB[jj][3];
                acc.x += w0 * v0.x + w1 * v1.x + w2 * v2.x + w3 * v3.x;
                acc.y += w0 * v0.y + w1 * v1.y + w2 * v2.y + w3 * v3.y;
                acc.z += w0 * v0.z + w1 * v1.z + w2 * v2.z + w3 * v3.z;
                acc.w += w0 * v0.w + w1 * v1.w + w2 * v2.w + w3 * v3.w;
            }
        }

        outp[(g + 0) * HW_ + t] = acc.x;
        outp[(g + 1) * HW_ + t] = acc.y;
        outp[(g + 2) * HW_ + t] = acc.z;
        outp[(g + 3) * HW_ + t] = acc.w;
    }
}

extern "C" void kernel_launch(void* const* d_in, const int* in_sizes, int n_in,
                              void* d_out, int out_size)
{
    const float* feat  = (const float*)d_in[0];   // [A*B, C, H, W] f32
    const float* trans = (const float*)d_in[1];   // [B, A, A, 4, 4] f32
    const int*   nag   = (const int*)d_in[2];     // [B, A] int32
    float* out = (float*)d_out;                   // [A*B, C, H, W] f32

    dim3 grid(C_ / CCHUNK, A_, B_);
    fuse_kernel<<<grid, 256>>>(feat, trans, nag, out);
}

// round 13
// speedup vs baseline: 1.5567x; 1.1595x over previous
#include <cuda_runtime.h>

#define B_ 16
#define A_ 5
#define C_ 512
#define HW_ 256
#define NC 4
#define CCHUNK 32
#define SMEM_BYTES (64 * 1024)

// out[(i*B+b)] = local[(i*B+b)] + sum_{j != i, j<n, i<n} warp(local[(j*B+b)], trans[b,i,j])
// warp = bilinear grid_sample chained twice (rotation, then constant translation),
// zero pad, align_corners=False. Geometry channel-invariant -> register tap tables.
// float4 channel-vectorized tiles. Cross-chunk software pipeline: stage2 of chunk
// k-1 runs in iteration k, tileA and tileR both ping-pong -> ONE __syncthreads per
// chunk. Next chunk's fills prefetched into registers. No swizzle (R12: broadcasts
// beat swizzle). Prologue issues chunk-0 LDGs before tap ALU to hide fill latency.

extern __shared__ float4 sm4[];
// tileA: [2][4][256] float4 at offset 0      (32KB)
// tileR: [2][4][256] float4 at offset 2048   (32KB)

__global__ __launch_bounds__(256, 2)
void fuse_kernel(const float* __restrict__ feat,
                 const float* __restrict__ trans,
                 const int* __restrict__ nag,
                 float* __restrict__ out)
{
    float4* __restrict__ tileA = sm4;
    float4* __restrict__ tileR = sm4 + 2048;

    const int b  = blockIdx.z;
    const int i  = blockIdx.y;
    const int c0 = blockIdx.x * CCHUNK;
    const int t  = threadIdx.x;
    const int x  = t & 15;
    const int y  = t >> 4;

    const int n = nag[b * A_];            // num_agent_tensor[b, 0]
    const bool active = (i < n) && (n > 1);

    const unsigned base = ((unsigned)(i * B_ + b) * C_ + c0) * HW_;
    const float* __restrict__ local = feat + base;
    float* __restrict__ outp        = out  + base;

    // ---- neighbor offsets + validity first (cheap), then issue chunk-0 LDGs ----
    unsigned off[4];
    bool valid[4];
    #pragma unroll
    for (int jj = 0; jj < 4; jj++) {
        const int j = jj + (jj >= i ? 1 : 0);          // skip j == i
        valid[jj] = active && (j < n);
        off[jj]   = ((unsigned)(j * B_ + b) * C_ + c0) * HW_;
    }

    float4 pre[4];
    #pragma unroll
    for (int jj = 0; jj < 4; jj++) {
        if (valid[jj]) {
            const float* src = feat + off[jj];
            pre[jj].x = src[t];
            pre[jj].y = src[HW_ + t];
            pre[jj].z = src[2 * HW_ + t];
            pre[jj].w = src[3 * HW_ + t];
        }
    }

    // ---- tap tables (ALU hides the LDGs above) ----
    const float xs = (2.f * (float)x + 1.f) / 16.f - 1.f;
    const float ys = (2.f * (float)y + 1.f) / 16.f - 1.f;

    float    wA[4][4], wB[4][4];
    unsigned pA[4], pB[4];                // 4 byte-indices packed per table

    #pragma unroll
    for (int jj = 0; jj < 4; jj++) {
        const int j = jj + (jj >= i ? 1 : 0);
        pA[jj] = 0u; pB[jj] = 0u;
        #pragma unroll
        for (int m = 0; m < 4; m++) { wA[jj][m] = 0.f; wB[jj][m] = 0.f; }
        if (valid[jj]) {
            const float* T = trans + (((b * A_ + i) * A_ + j) * 16);
            const float t00 = T[0], t01 = T[1], t03 = T[3];
            const float t10 = T[4], t11 = T[5], t13 = T[7];

            // ---- stage 1: rotation grid ----
            const float gx = t00 * xs + t01 * ys;
            const float gy = t10 * xs + t11 * ys;
            const float ix = ((gx + 1.f) * 16.f - 1.f) * 0.5f;
            const float iy = ((gy + 1.f) * 16.f - 1.f) * 0.5f;
            const float x0f = floorf(ix), y0f = floorf(iy);
            const float fx = ix - x0f,  fy = iy - y0f;
            const int x0 = (int)x0f, y0 = (int)y0f;
            #pragma unroll
            for (int m = 0; m < 4; m++) {
                const int dx = m & 1, dy = m >> 1;
                const int xi = x0 + dx, yi = y0 + dy;
                const float w = (dx ? fx : 1.f - fx) * (dy ? fy : 1.f - fy);
                const bool in = (xi >= 0) & (xi < 16) & (yi >= 0) & (yi < 16);
                wA[jj][m] = in ? w : 0.f;
                pA[jj]  |= (unsigned)(in ? (yi * 16 + xi) : 0) << (8 * m);
            }

            // ---- stage 2: translation grid ----
            const float xt = t03 * (1.f / 32.f);      // 4*T03/128
            const float yt = -t13 * (1.f / 32.f);
            const float ix2 = ((xs + xt + 1.f) * 16.f - 1.f) * 0.5f;
            const float iy2 = ((ys + yt + 1.f) * 16.f - 1.f) * 0.5f;
            const float x20f = floorf(ix2), y20f = floorf(iy2);
            const float fx2 = ix2 - x20f,  fy2 = iy2 - y20f;
            const int x20 = (int)x20f, y20 = (int)y20f;
            #pragma unroll
            for (int m = 0; m < 4; m++) {
                const int dx = m & 1, dy = m >> 1;
                const int xi = x20 + dx, yi = y20 + dy;
                const float w = (dx ? fx2 : 1.f - fx2) * (dy ? fy2 : 1.f - fy2);
                const bool in = (xi >= 0) & (xi < 16) & (yi >= 0) & (yi < 16);
                wB[jj][m] = in ? w : 0.f;
                pB[jj]  |= (unsigned)(in ? (yi * 16 + xi) : 0) << (8 * m);
            }
        }
    }

    // ---- pipelined main loop: one __syncthreads per chunk ----
    float4 accP;                          // accumulator of the previous chunk
    int gP = 0;                           // previous chunk's channel base

    for (int k = 0, g = 0; g < CCHUNK; g += NC, k++) {
        const int p = k & 1;
        // deposit prefetched fills (STS.128, conflict-free)
        #pragma unroll
        for (int jj = 0; jj < 4; jj++) {
            if (valid[jj]) tileA[(p * 4 + jj) * 256 + t] = pre[jj];
        }

        float4 accC;
        accC.x = local[(g + 0) * HW_ + t];
        accC.y = local[(g + 1) * HW_ + t];
        accC.z = local[(g + 2) * HW_ + t];
        accC.w = local[(g + 3) * HW_ + t];

        __syncthreads();   // covers: tileA[p] RAW (this chunk), tileR[p^1] RAW (prev chunk)

        // prefetch next chunk's fills
        if (g + NC < CCHUNK) {
            #pragma unroll
            for (int jj = 0; jj < 4; jj++) {
                if (valid[jj]) {
                    const float* src = feat + off[jj] + (unsigned)(g + NC) * HW_;
                    pre[jj].x = src[t];
                    pre[jj].y = src[HW_ + t];
                    pre[jj].z = src[2 * HW_ + t];
                    pre[jj].w = src[3 * HW_ + t];
                }
            }
        }

        // stage 1 (chunk k): rotation sample tileA[p] -> tileR[p]
        #pragma unroll
        for (int jj = 0; jj < 4; jj++) {
            if (valid[jj]) {
                const int tb = (p * 4 + jj) * 256;
                const float4 v0 = tileA[tb + ((pA[jj]      ) & 255)];
                const float4 v1 = tileA[tb + ((pA[jj] >>  8) & 255)];
                const float4 v2 = tileA[tb + ((pA[jj] >> 16) & 255)];
                const float4 v3 = tileA[tb + ((pA[jj] >> 24) & 255)];
                const float w0 = wA[jj][0], w1 = wA[jj][1], w2 = wA[jj][2], w3 = wA[jj][3];
                float4 r;
                r.x = w0 * v0.x + w1 * v1.x + w2 * v2.x + w3 * v3.x;
                r.y = w0 * v0.y + w1 * v1.y + w2 * v2.y + w3 * v3.y;
                r.z = w0 * v0.z + w1 * v1.z + w2 * v2.z + w3 * v3.z;
                r.w = w0 * v0.w + w1 * v1.w + w2 * v2.w + w3 * v3.w;
                tileR[(p * 4 + jj) * 256 + t] = r;
            }
        }

        // stage 2 (chunk k-1): translation sample tileR[p^1] -> accumulate + store
        if (k > 0) {
            const int q = (k - 1) & 1;
            #pragma unroll
            for (int jj = 0; jj < 4; jj++) {
                if (valid[jj]) {
                    const int rb = (q * 4 + jj) * 256;
                    const float4 v0 = tileR[rb + ((pB[jj]      ) & 255)];
                    const float4 v1 = tileR[rb + ((pB[jj] >>  8) & 255)];
                    const float4 v2 = tileR[rb + ((pB[jj] >> 16) & 255)];
                    const float4 v3 = tileR[rb + ((pB[jj] >> 24) & 255)];
                    const float w0 = wB[jj][0], w1 = wB[jj][1], w2 = wB[jj][2], w3 = wB[jj][3];
                    accP.x += w0 * v0.x + w1 * v1.x + w2 * v2.x + w3 * v3.x;
                    accP.y += w0 * v0.y + w1 * v1.y + w2 * v2.y + w3 * v3.y;
                    accP.z += w0 * v0.z + w1 * v1.z + w2 * v2.z + w3 * v3.z;
                    accP.w += w0 * v0.w + w1 * v1.w + w2 * v2.w + w3 * v3.w;
                }
            }
            __stcs(&outp[(gP + 0) * HW_ + t], accP.x);
            __stcs(&outp[(gP + 1) * HW_ + t], accP.y);
            __stcs(&outp[(gP + 2) * HW_ + t], accP.z);
            __stcs(&outp[(gP + 3) * HW_ + t], accP.w);
        }
        accP = accC;
        gP = g;
    }

    // ---- epilogue: drain stage 2 of the last chunk ----
    __syncthreads();
    {
        const int q = ((CCHUNK / NC) - 1) & 1;
        #pragma unroll
        for (int jj = 0; jj < 4; jj++) {
            if (valid[jj]) {
                const int rb = (q * 4 + jj) * 256;
                const float4 v0 = tileR[rb + ((pB[jj]      ) & 255)];
                const float4 v1 = tileR[rb + ((pB[jj] >>  8) & 255)];
                const float4 v2 = tileR[rb + ((pB[jj] >> 16) & 255)];
                const float4 v3 = tileR[rb + ((pB[jj] >> 24) & 255)];
                const float w0 = wB[jj][0], w1 = wB[jj][1], w2 = wB[jj][2], w3 = wB[jj][3];
                accP.x += w0 * v0.x + w1 * v1.x + w2 * v2.x + w3 * v3.x;
                accP.y += w0 * v0.y + w1 * v1.y + w2 * v2.y + w3 * v3.y;
                accP.z += w0 * v0.z + w1 * v1.z + w2 * v2.z + w3 * v3.z;
                accP.w += w0 * v0.w + w1 * v1.w + w2 * v2.w + w3 * v3.w;
            }
        }
        __stcs(&outp[(gP + 0) * HW_ + t], accP.x);
        __stcs(&outp[(gP + 1) * HW_ + t], accP.y);
        __stcs(&outp[(gP + 2) * HW_ + t], accP.z);
        __stcs(&outp[(gP + 3) * HW_ + t], accP.w);
    }
}

extern "C" void kernel_launch(void* const* d_in, const int* in_sizes, int n_in,
                              void* d_out, int out_size)
{
    const float* feat  = (const float*)d_in[0];   // [A*B, C, H, W] f32
    const float* trans = (const float*)d_in[1];   // [B, A, A, 4, 4] f32
    const int*   nag   = (const int*)d_in[2];     // [B, A] int32
    float* out = (float*)d_out;                   // [A*B, C, H, W] f32

    static int attr_set = 0;
    if (!attr_set) {
        cudaFuncSetAttribute(fuse_kernel,
                             cudaFuncAttributeMaxDynamicSharedMemorySize, SMEM_BYTES);
        attr_set = 1;
    }

    dim3 grid(C_ / CCHUNK, A_, B_);
    fuse_kernel<<<grid, 256, SMEM_BYTES>>>(feat, trans, nag, out);
}